// round 2
// baseline (speedup 1.0000x reference)
#include <cuda_runtime.h>
#include <math.h>

#define DIM   256
#define KBINS 5
#define BTAIL 3.0f

// Shared param tables (SoA, [.. ][DIM] -> bank = col % 32, conflict-free)
__global__ __launch_bounds__(256) void rqs_forward_kernel(
    const float* __restrict__ u,
    const float* __restrict__ w,
    const float* __restrict__ h,
    const float* __restrict__ d,
    float* __restrict__ xout,
    float* __restrict__ ldout,
    int batch)
{
    __shared__ float s_knot[KBINS - 1][DIM];   // interior knots cum_w[1..K-1]
    __shared__ float s_xk[KBINS][DIM];
    __shared__ float s_wi[KBINS][DIM];         // 1/width
    __shared__ float s_yk[KBINS][DIM];
    __shared__ float s_hk[KBINS][DIM];
    __shared__ float s_dk[KBINS][DIM];
    __shared__ float s_d1[KBINS][DIM];

    const int tid = threadIdx.x;

    // ---- per-dim spline parameter precompute (one thread per dim) ----
    {
        const int dm = tid;  // blockDim.x == DIM
        float wv[KBINS], hv[KBINS], dv[KBINS - 1];
#pragma unroll
        for (int i = 0; i < KBINS; i++) {
            wv[i] = w[dm * KBINS + i];
            hv[i] = h[dm * KBINS + i];
        }
#pragma unroll
        for (int i = 0; i < KBINS - 1; i++) dv[i] = d[dm * (KBINS - 1) + i];

        // softmax(w) * 2B  -> widths; cumsum -> knot x positions
        float mw = wv[0];
#pragma unroll
        for (int i = 1; i < KBINS; i++) mw = fmaxf(mw, wv[i]);
        float ew[KBINS], sw = 0.f;
#pragma unroll
        for (int i = 0; i < KBINS; i++) { ew[i] = expf(wv[i] - mw); sw += ew[i]; }
        float widths[KBINS];
        float inv_sw = (2.0f * BTAIL) / sw;
#pragma unroll
        for (int i = 0; i < KBINS; i++) widths[i] = ew[i] * inv_sw;

        float mh = hv[0];
#pragma unroll
        for (int i = 1; i < KBINS; i++) mh = fmaxf(mh, hv[i]);
        float eh[KBINS], sh = 0.f;
#pragma unroll
        for (int i = 0; i < KBINS; i++) { eh[i] = expf(hv[i] - mh); sh += eh[i]; }
        float heights[KBINS];
        float inv_sh = (2.0f * BTAIL) / sh;
#pragma unroll
        for (int i = 0; i < KBINS; i++) heights[i] = eh[i] * inv_sh;

        float xs[KBINS + 1], ys[KBINS + 1];
        xs[0] = -BTAIL; ys[0] = -BTAIL;
#pragma unroll
        for (int i = 0; i < KBINS; i++) {
            xs[i + 1] = xs[i] + widths[i];
            ys[i + 1] = ys[i] + heights[i];
        }
        xs[KBINS] = BTAIL;  // match reference's exact-endpoint set
        ys[KBINS] = BTAIL;

        float derivs[KBINS + 1];
        derivs[0] = 1.0f;
#pragma unroll
        for (int i = 0; i < KBINS - 1; i++) derivs[i + 1] = log1pf(expf(dv[i]));  // softplus
        derivs[KBINS] = 1.0f;

#pragma unroll
        for (int k = 0; k < KBINS - 1; k++) s_knot[k][dm] = xs[k + 1];
#pragma unroll
        for (int b = 0; b < KBINS; b++) {
            s_xk[b][dm] = xs[b];
            s_wi[b][dm] = 1.0f / widths[b];
            s_yk[b][dm] = ys[b];
            s_hk[b][dm] = heights[b];
            s_dk[b][dm] = derivs[b];
            s_d1[b][dm] = derivs[b + 1];
        }
    }
    __syncthreads();

    // ---- mainloop: one warp per row; lane l covers cols l+32j ----
    const int lane = tid & 31;
    const int warp = tid >> 5;
    const int gw = blockIdx.x * (blockDim.x >> 5) + warp;
    const int nw = gridDim.x * (blockDim.x >> 5);

    for (int row = gw; row < batch; row += nw) {
        const float* __restrict__ ur = u + (size_t)row * DIM;
        float* __restrict__ xr = xout + (size_t)row * DIM;

        float uv[8];
#pragma unroll
        for (int j = 0; j < 8; j++) uv[j] = ur[lane + 32 * j];  // MLP=8, coalesced

        float acc = 0.0f;
#pragma unroll
        for (int j = 0; j < 8; j++) {
            const int col = lane + 32 * j;
            const float uu = uv[j];
            const float uc = fminf(fmaxf(uu, -BTAIL), BTAIL);
            const bool inside = (fabsf(uu) <= BTAIL);

            int idx = (uc >= s_knot[0][col]) + (uc >= s_knot[1][col])
                    + (uc >= s_knot[2][col]) + (uc >= s_knot[3][col]);

            const float xk = s_xk[idx][col];
            const float wi = s_wi[idx][col];
            const float yk = s_yk[idx][col];
            const float hk = s_hk[idx][col];
            const float dk = s_dk[idx][col];
            const float d1 = s_d1[idx][col];

            const float delta = hk * wi;
            const float th    = (uc - xk) * wi;
            const float omt   = 1.0f - th;
            const float t1m   = th * omt;
            const float th2   = th * th;
            const float sgap  = dk + d1 - 2.0f * delta;
            const float denom = fmaf(sgap, t1m, delta);
            const float r     = __fdividef(1.0f, denom);

            const float num = hk * fmaf(delta, th2, dk * t1m);
            const float xin = fmaf(num, r, yk);

            const float ldnum = (delta * delta) *
                fmaf(d1, th2, fmaf(2.0f * delta, t1m, dk * omt * omt));
            const float ldin = __logf(ldnum * r * r);  // log(ldnum) - 2 log(denom)

            xr[col] = inside ? xin : uu;
            acc += inside ? ldin : 0.0f;
        }

        // warp reduce logdet
#pragma unroll
        for (int o = 16; o > 0; o >>= 1) acc += __shfl_xor_sync(0xffffffffu, acc, o);
        if (lane == 0) ldout[row] = acc;
    }
}

extern "C" void kernel_launch(void* const* d_in, const int* in_sizes, int n_in,
                              void* d_out, int out_size)
{
    const float* u = (const float*)d_in[0];
    const float* w = (const float*)d_in[1];
    const float* h = (const float*)d_in[2];
    const float* d = (const float*)d_in[3];

    const int batch = in_sizes[0] / DIM;

    float* xout  = (float*)d_out;
    float* ldout = (float*)d_out + (size_t)batch * DIM;

    const int threads = 256;
    const int grid = 896;  // ~6 blocks/SM by smem (35KB), grid-stride covers all rows
    rqs_forward_kernel<<<grid, threads>>>(u, w, h, d, xout, ldout, batch);
}

// round 4
// speedup vs baseline: 1.1620x; 1.1620x over previous
#include <cuda_runtime.h>
#include <math.h>

#define DIM   256
#define KBINS 5
#define BTAIL 3.0f

__global__ __launch_bounds__(256) void rqs_forward_kernel(
    const float* __restrict__ u,
    const float* __restrict__ w,
    const float* __restrict__ h,
    const float* __restrict__ d,
    float* __restrict__ xout,
    float* __restrict__ ldout,
    int batch)
{
    // Packed tables: per-lane 16B chunks, contiguous across lanes -> conflict-free LDS.128
    __shared__ float4 s_kn[DIM];              // interior knots {x1,x2,x3,x4}
    __shared__ float4 s_pa[KBINS][DIM];       // {xk, 1/wk, hk, dk}
    __shared__ float4 s_pb[KBINS][DIM];       // {yk, dk1, delta, sgap}

    const int tid = threadIdx.x;

    // ---- per-dim spline parameter precompute (one thread per dim) ----
    {
        const int dm = tid;
        float wv[KBINS], hv[KBINS], dv[KBINS - 1];
#pragma unroll
        for (int i = 0; i < KBINS; i++) {
            wv[i] = w[dm * KBINS + i];
            hv[i] = h[dm * KBINS + i];
        }
#pragma unroll
        for (int i = 0; i < KBINS - 1; i++) dv[i] = d[dm * (KBINS - 1) + i];

        float mw = wv[0];
#pragma unroll
        for (int i = 1; i < KBINS; i++) mw = fmaxf(mw, wv[i]);
        float ew[KBINS], sw = 0.f;
#pragma unroll
        for (int i = 0; i < KBINS; i++) { ew[i] = expf(wv[i] - mw); sw += ew[i]; }
        float widths[KBINS];
        float inv_sw = (2.0f * BTAIL) / sw;
#pragma unroll
        for (int i = 0; i < KBINS; i++) widths[i] = ew[i] * inv_sw;

        float mh = hv[0];
#pragma unroll
        for (int i = 1; i < KBINS; i++) mh = fmaxf(mh, hv[i]);
        float eh[KBINS], sh = 0.f;
#pragma unroll
        for (int i = 0; i < KBINS; i++) { eh[i] = expf(hv[i] - mh); sh += eh[i]; }
        float heights[KBINS];
        float inv_sh = (2.0f * BTAIL) / sh;
#pragma unroll
        for (int i = 0; i < KBINS; i++) heights[i] = eh[i] * inv_sh;

        float xs[KBINS + 1], ys[KBINS + 1];
        xs[0] = -BTAIL; ys[0] = -BTAIL;
#pragma unroll
        for (int i = 0; i < KBINS; i++) {
            xs[i + 1] = xs[i] + widths[i];
            ys[i + 1] = ys[i] + heights[i];
        }
        xs[KBINS] = BTAIL;
        ys[KBINS] = BTAIL;

        float derivs[KBINS + 1];
        derivs[0] = 1.0f;
#pragma unroll
        for (int i = 0; i < KBINS - 1; i++) derivs[i + 1] = log1pf(expf(dv[i]));
        derivs[KBINS] = 1.0f;

        s_kn[dm] = make_float4(xs[1], xs[2], xs[3], xs[4]);
#pragma unroll
        for (int b = 0; b < KBINS; b++) {
            float wi    = 1.0f / widths[b];
            float delta = heights[b] / widths[b];
            float sgap  = derivs[b] + derivs[b + 1] - 2.0f * delta;
            s_pa[b][dm] = make_float4(xs[b], wi, heights[b], derivs[b]);
            s_pb[b][dm] = make_float4(ys[b], derivs[b + 1], delta, sgap);
        }
    }
    __syncthreads();

    // ---- mainloop: one warp per row; lane l covers cols l+32j ----
    const int lane = tid & 31;
    const int warp = tid >> 5;
    const int gw = blockIdx.x * (blockDim.x >> 5) + warp;
    const int nw = gridDim.x * (blockDim.x >> 5);

    for (int row = gw; row < batch; row += nw) {
        const float* __restrict__ ur = u + (size_t)row * DIM;
        float* __restrict__ xr = xout + (size_t)row * DIM;

        float uv[8];
#pragma unroll
        for (int j = 0; j < 8; j++) uv[j] = ur[lane + 32 * j];  // coalesced, MLP=8

        int   esum  = 0;
        float mprod = 1.0f;
#pragma unroll
        for (int j = 0; j < 8; j++) {
            const int col = lane + 32 * j;
            const float uu = uv[j];
            const float uc = fminf(fmaxf(uu, -BTAIL), BTAIL);
            const bool inside = (fabsf(uu) <= BTAIL);

            const float4 kn = s_kn[col];
            int idx = (uc >= kn.x) + (uc >= kn.y) + (uc >= kn.z) + (uc >= kn.w);

            const float4 pa = s_pa[idx][col];  // {xk, wi, hk, dk}
            const float4 pb = s_pb[idx][col];  // {yk, d1, delta, sgap}

            const float th   = (uc - pa.x) * pa.y;
            const float omt  = 1.0f - th;
            const float t1m  = th * omt;
            const float th2  = th * th;
            const float denom = fmaf(pb.w, t1m, pb.z);
            const float r     = __fdividef(1.0f, denom);

            const float num = pa.z * fmaf(pb.z, th2, pa.w * t1m);
            const float xin = fmaf(num, r, pb.x);

            const float dd   = pb.z * pb.z;          // delta^2
            const float core = fmaf(pb.y, th2,
                               fmaf(pb.z + pb.z, t1m, pa.w * omt * omt));
            const float t = inside ? (dd * core) * (r * r) : 1.0f;

            // split-accumulate log: exponent sum (int) + mantissa product [1,2)
            const unsigned bt = __float_as_uint(t);
            esum  += (int)(bt >> 23);
            mprod *= __uint_as_float((bt & 0x007FFFFFu) | 0x3F800000u);

            xr[col] = inside ? xin : uu;
        }

        float part = __log2f(mprod) + (float)(esum - 8 * 127);
#pragma unroll
        for (int o = 16; o > 0; o >>= 1) part += __shfl_xor_sync(0xffffffffu, part, o);
        if (lane == 0) ldout[row] = part * 0.6931471805599453f;  // ln(2)
    }
}

extern "C" void kernel_launch(void* const* d_in, const int* in_sizes, int n_in,
                              void* d_out, int out_size)
{
    const float* u = (const float*)d_in[0];
    const float* w = (const float*)d_in[1];
    const float* h = (const float*)d_in[2];
    const float* d = (const float*)d_in[3];

    const int batch = in_sizes[0] / DIM;

    float* xout  = (float*)d_out;
    float* ldout = (float*)d_out + (size_t)batch * DIM;

    const int threads = 256;
    const int grid = 896;
    rqs_forward_kernel<<<grid, threads>>>(u, w, h, d, xout, ldout, batch);
}